// round 12
// baseline (speedup 1.0000x reference)
#include <cuda_runtime.h>

// PBKDF2-toy, serial single-warp kernel, R12: 4-byte SWAR packing.
// Settled model (R5/R8/R11): single-warp floor = TOTAL issue slots (~311/
// iter now); pipe split irrelevant. SWAR cuts the count: state packed 4
// consecutive bytes/reg (R[0..7]). Mix taps +11/+17 have min forward
// dependence 15, so 4-step groups (one reg) vectorize, groups in order.
// Per dest reg: 2 PRMT tap gathers + exact byte-wise mod-256 add
// (s=(A&7f)+(B&7f); fix=(A^B)&80; R^=s^fix -- final is one LOP3) = 7 ops/
// 4 bytes. Absorb: 4 regs x 4 ops (c-masks hoisted). F-fold: 8 LOP3 (was
// 32). 248 slots/iter vs 311. Harness shims: float out, sniffed in (R3).

__device__ __forceinline__ unsigned load_byte(const void* p, int i) {
    int v = ((const int*)p)[i];
    if ((unsigned)v <= 255u) return (unsigned)v;   // int32 input
    return (unsigned)(int)__int_as_float(v);       // float32 input
}

#define M7 0x7f7f7f7fu
#define M8 0x80808080u

__global__ void __launch_bounds__(32, 1)
Model_62955630625117_kernel(const void* __restrict__ pw_in,
                            const void* __restrict__ salt_in,
                            float* __restrict__ out) {
    // ---- Scalar prologue: U0 (one-time, reuses validated path) ----
    unsigned c[16], r[32];
    #pragma unroll
    for (int j = 0; j < 16; j++) {
        unsigned p = load_byte(pw_in, j);
        c[j] = (p * 31u) & 255u;
        r[j] = p;
    }
    #pragma unroll
    for (int j = 0; j < 16; j++) r[16 + j] = load_byte(salt_in, j);
    // First hmac message = salt(16) ++ block_num{0,0,0,1}
    r[0] = c[0];
    r[1] = c[1];
    r[2] = c[2];
    r[3] = (c[3] + 1u) & 255u;
    #pragma unroll
    for (int rd = 0; rd < 4; rd++) {
        #pragma unroll
        for (int i = 0; i < 32; i++)
            r[i] = (r[i] ^ (r[(i + 17) & 31] + r[(i + 11) & 31])) & 255u;
    }

    // ---- Pack: R[k] = bytes 4k..4k+3 of U; Cp = packed key contribution ----
    unsigned R[8], Fq[8], Cp[4], C7[4];
    #pragma unroll
    for (int k = 0; k < 8; k++) {
        R[k] = r[4 * k] | (r[4 * k + 1] << 8) | (r[4 * k + 2] << 16) | (r[4 * k + 3] << 24);
        Fq[k] = R[k];                     // F init = U0
    }
    #pragma unroll
    for (int k = 0; k < 4; k++) {
        Cp[k] = c[4 * k] | (c[4 * k + 1] << 8) | (c[4 * k + 2] << 16) | (c[4 * k + 3] << 24);
        C7[k] = Cp[k] & M7;               // hoisted carry-mask of c
    }

    // ---- 999 packed iterations ----
    // absorb: newR[k] = Cp[k] (+)byte R[k+4]; newR[k+4] = R[k]  (order-2 swap)
    // mix: 4 rounds x 8 reg-groups in order; group d:
    //   A = bytes 4d+11.. : PRMT(R[d+2], R[d+3], 0x6543)
    //   B = bytes 4d+17.. : PRMT(R[d+4], R[d+5], 0x4321)
    //   R[d] ^= byteadd(A,B)   (exact SWAR mod-256, final xor3 = 1 LOP3)
    #pragma unroll 4
    for (int it = 1; it < 1000; it++) {
        #pragma unroll
        for (int k = 0; k < 4; k++) {
            unsigned x = R[k + 4];
            unsigned s = C7[k] + (x & M7);
            unsigned f = (Cp[k] ^ x) & M8;
            R[k + 4] = R[k];
            R[k] = s ^ f;
        }
        #pragma unroll
        for (int rd = 0; rd < 4; rd++) {
            #pragma unroll
            for (int d = 0; d < 8; d++) {
                unsigned A = __byte_perm(R[(d + 2) & 7], R[(d + 3) & 7], 0x6543);
                unsigned B = __byte_perm(R[(d + 4) & 7], R[(d + 5) & 7], 0x4321);
                unsigned s = (A & M7) + (B & M7);
                unsigned f = (A ^ B) & M8;
                R[d] = R[d] ^ s ^ f;      // LOP3 (xor3); bytes stay clean
            }
        }
        #pragma unroll
        for (int k = 0; k < 8; k++) Fq[k] ^= R[k];
    }

    if (threadIdx.x == 0) {
        #pragma unroll
        for (int i = 0; i < 32; i++)
            out[i] = (float)((Fq[i >> 2] >> (8 * (i & 3))) & 255u);
    }
}

extern "C" void kernel_launch(void* const* d_in, const int* in_sizes, int n_in,
                              void* d_out, int out_size) {
    const void* password = d_in[0];
    const void* salt     = (n_in >= 2) ? d_in[1] : (const void*)((const int*)d_in[0] + 16);
    float* out           = (float*)d_out;
    Model_62955630625117_kernel<<<1, 32>>>(password, salt, out);
}

// round 13
// speedup vs baseline: 1.1468x; 1.1468x over previous
#include <cuda_runtime.h>

// PBKDF2-toy, serial single-warp register kernel. R13: stall-placement
// experiment on the best config (R8, 184.4us). Model: cycles/iter =
// max(2*alu_class, total_issue) + seam stalls; R8's floor ~288-320 with
// ~30-60 stall at the round4 -> absorb seam (round-4 outputs feed next
// absorb directly, and R8 also fused all 32 F-ops right there). Change:
// fold U_{k-1} DURING iteration k's absorb (old lo/hi both live across the
// swap), init F=0, fold U_999 after the loop. Identical op mix (16 IMAD
// pack16 + 16 LOP3), moved to the thin fully-parallel absorb region.
// SWAR permanently rejected (R12: PRMT/AND are alu-class, 204 alu -> 416
// cyc/iter). Harness shims: float32 out, dtype-sniffed in (proven R3).

__device__ __forceinline__ unsigned load_byte(const void* p, int i) {
    int v = ((const int*)p)[i];
    if ((unsigned)v <= 255u) return (unsigned)v;   // int32 input
    return (unsigned)(int)__int_as_float(v);       // float32 input
}

// hi*65536 + lo as a single IMAD (fma pipe); benign to scheduling (R8).
__device__ __forceinline__ unsigned pack16(unsigned hi, unsigned lo) {
    unsigned t;
    asm("mad.lo.u32 %0, %1, 65536, %2;" : "=r"(t) : "r"(hi), "r"(lo));
    return t;
}

__global__ void __launch_bounds__(32, 1)
Model_62955630625117_kernel(const void* __restrict__ pw_in,
                            const void* __restrict__ salt_in,
                            float* __restrict__ out) {
    // All lanes uniform & convergent; lane 0 writes at the end.
    unsigned c[16];    // (pw[j]*31) & 255, loop-invariant
    unsigned r[32];    // hash state U (mix LOP3 keeps bytes 8-bit)
    unsigned Fp[16];   // packed xor accumulator: lo16 = F[j], hi16 = F[j+16]

    #pragma unroll
    for (int j = 0; j < 16; j++) {
        unsigned p = load_byte(pw_in, j);
        c[j] = (p * 31u) & 255u;
        r[j] = p;
        Fp[j] = 0u;                       // F accumulates U0..U998 in-loop
    }
    #pragma unroll
    for (int j = 0; j < 16; j++) r[16 + j] = load_byte(salt_in, j);

    // First hmac message = salt(16) ++ block_num{0,0,0,1}
    r[0] = c[0];
    r[1] = c[1];
    r[2] = c[2];
    r[3] = (c[3] + 1u) & 255u;

    // U0 mix
    #pragma unroll
    for (int rd = 0; rd < 4; rd++) {
        #pragma unroll
        for (int i = 0; i < 32; i++)
            r[i] = (r[i] ^ (r[(i + 17) & 31] + r[(i + 11) & 31])) & 255u;
    }

    // 999 chained iterations. At loop top r = U_{it-1}; the absorb swap has
    // both old halves live, so U_{it-1} is folded into Fp right here (thin,
    // fully-parallel region) instead of at the round-4 seam.
    // Absorb collapse: r[j] = c[j] + r[16+j] (9-bit OK, mix LOP3 re-masks),
    // r[16+j] = old r[j] (order-2 swap; unroll 4 -> pure renaming).
    #pragma unroll 4
    for (int it = 1; it < 1000; it++) {
        #pragma unroll
        for (int j = 0; j < 16; j++) {
            unsigned lo = r[j];
            unsigned hi = r[16 + j];
            Fp[j] ^= pack16(hi, lo);      // fold U_{it-1}: IMAD + LOP3
            r[j] = c[j] + hi;
            r[16 + j] = lo;
        }
        #pragma unroll
        for (int rd = 0; rd < 4; rd++) {
            #pragma unroll
            for (int i = 0; i < 32; i++)
                r[i] = (r[i] ^ (r[(i + 17) & 31] + r[(i + 11) & 31])) & 255u;
        }
    }
    // fold the last state U_999
    #pragma unroll
    for (int j = 0; j < 16; j++)
        Fp[j] ^= pack16(r[16 + j], r[j]);

    if (threadIdx.x == 0) {
        #pragma unroll
        for (int j = 0; j < 16; j++) {
            out[j]      = (float)(Fp[j] & 0xFFFFu);
            out[j + 16] = (float)(Fp[j] >> 16);
        }
    }
}

extern "C" void kernel_launch(void* const* d_in, const int* in_sizes, int n_in,
                              void* d_out, int out_size) {
    const void* password = d_in[0];
    const void* salt     = (n_in >= 2) ? d_in[1] : (const void*)((const int*)d_in[0] + 16);
    float* out           = (float*)d_out;
    Model_62955630625117_kernel<<<1, 32>>>(password, salt, out);
}